// round 14
// baseline (speedup 1.0000x reference)
#include <cuda_runtime.h>
#include <cuda_bf16.h>
#include <math.h>
#include <cstdint>

#define PI_F 3.14159265358979323846f

// ===================== helpers ==============================================
__device__ __forceinline__ uint32_t smem_u32(const void* p){
  uint32_t a;
  asm("{ .reg .u64 t; cvta.to.shared.u64 t, %1; cvt.u32.u64 %0, t; }"
      : "=r"(a) : "l"(p));
  return a;
}
__device__ __forceinline__ void ldsm_x4(uint32_t &r0, uint32_t &r1,
                                        uint32_t &r2, uint32_t &r3, uint32_t addr){
  asm volatile("ldmatrix.sync.aligned.m8n8.x4.shared.b16 {%0,%1,%2,%3}, [%4];"
               : "=r"(r0), "=r"(r1), "=r"(r2), "=r"(r3) : "r"(addr));
}
__device__ __forceinline__ void mma_bf16(float d[4], const uint32_t a[4],
                                         const uint32_t b[2]){
  asm volatile("mma.sync.aligned.m16n8k16.row.col.f32.bf16.bf16.f32 "
    "{%0,%1,%2,%3}, {%4,%5,%6,%7}, {%8,%9}, {%0,%1,%2,%3};"
    : "+f"(d[0]), "+f"(d[1]), "+f"(d[2]), "+f"(d[3])
    : "r"(a[0]), "r"(a[1]), "r"(a[2]), "r"(a[3]), "r"(b[0]), "r"(b[1]));
}
__device__ __forceinline__ unsigned long long ffma2(unsigned long long a,
                                                    unsigned long long b,
                                                    unsigned long long c){
  unsigned long long d;
  asm("fma.rn.f32x2 %0, %1, %2, %3;" : "=l"(d) : "l"(a), "l"(b), "l"(c));
  return d;
}
__device__ __forceinline__ unsigned long long dup2(float v){
  unsigned long long d; unsigned int u = __float_as_uint(v);
  asm("mov.b64 %0, {%1, %1};" : "=l"(d) : "r"(u));
  return d;
}
__device__ __forceinline__ float2 cmulf(float2 a, float2 b){
  return make_float2(a.x*b.x - a.y*b.y, a.x*b.y + a.y*b.x);
}
__device__ __forceinline__ void split_bf(float f, __nv_bfloat16 &h, __nv_bfloat16 &l){
  h = __float2bfloat16(f);
  l = __float2bfloat16(f - __bfloat162float(h));
}
__device__ __forceinline__ void fold_cs(int u, int ip, float &sumc, float &sumns){
  sumc = 0.f; sumns = 0.f;
  int iv[3]; int n = 0;
  iv[n++] = ip + 4;
  if (ip >= 124) iv[n++] = ip - 124;
  if (ip <= 3)   iv[n++] = ip + 132;
  for (int t = 0; t < n; t++){
    int m = (u * iv[t]) % 136;
    float s, c;
    sincosf((2.f*PI_F/136.f) * (float)m, &s, &c);
    sumc += c; sumns -= s;
  }
}

// ===================== persistent scratch ===================================
static __device__ __align__(16) __nv_bfloat16 g_Tbh[256*136*256]; // Tsp hi
static __device__ __align__(16) __nv_bfloat16 g_Tbl[256*136*256]; // Tsp lo
static __device__ float  g_Yt[256*138*136];                 // [b][n 138][u 136]
static __device__ float2 g_H [64*4*69*136];                 // [c][r][kw][kh]
static __device__ __align__(16) __nv_bfloat16 g_Zh[256*276*272];
static __device__ __align__(16) __nv_bfloat16 g_Zl[256*276*272];
static __device__ __align__(16) __nv_bfloat16 g_UAh[1024*128*144];
static __device__ __align__(16) __nv_bfloat16 g_UAl[1024*128*144];
static __device__ float  g_MB1[272*128];
static __device__ __align__(16) __nv_bfloat16 g_MB2th[144*256];  // MB2^T split
static __device__ __align__(16) __nv_bfloat16 g_MB2tl[144*256];
static __device__ __align__(16) __nv_bfloat16 g_MI1h[256*272];
static __device__ __align__(16) __nv_bfloat16 g_MI1l[256*272];
static __device__ __align__(16) __nv_bfloat16 g_MI2h[128*144];
static __device__ __align__(16) __nv_bfloat16 g_MI2l[128*144];
static __device__ float2 g_tw[272];

// ===================== merged builder =======================================
__global__ void k_build(){
  int idx = blockIdx.x*blockDim.x + threadIdx.x;
  if (idx < 272){
    float s, c; sincosf((2.f*PI_F/272.f)*(float)idx, &s, &c);
    g_tw[idx] = make_float2(c, s);
    return;
  }
  int i1 = idx - 272;
  if (i1 < 272*128){
    int col = i1 % 128, row = i1 / 128;
    int u = (row < 136) ? row : row - 136;
    float sc, sn; fold_cs(u, col, sc, sn);
    g_MB1[i1] = (row < 136) ? sc : sn;
    return;
  }
  int i2 = i1 - 272*128;
  if (i2 < 144*256){                       // MB2^T split: [n][k]
    int k = i2 % 256, n = i2 / 256;
    float val = 0.f;
    if (n < 138){
      int v  = (n < 69) ? n : n - 69;
      int jp = (k < 128) ? k : k - 128;
      float sc, sn; fold_cs(v, jp, sc, sn);
      if (n < 69) val = (k < 128) ? sc : -sn;
      else        val = (k < 128) ? sn :  sc;
    }
    split_bf(val, g_MB2th[i2], g_MB2tl[i2]);
    return;
  }
  int i3 = i2 - 144*256;
  if (i3 < 256*272){
    int k = i3 % 272, row = i3 / 272;
    int m   = (row & 127) + 4;
    int kap = (k < 136) ? k : k - 136;
    int a = (m * kap) % 136;
    float s, c; sincosf((2.f*PI_F/136.f)*(float)a, &s, &c);
    float val;
    if (row < 128) val = (k < 136) ?  c : -s;
    else           val = (k < 136) ?  s :  c;
    split_bf(val, g_MI1h[i3], g_MI1l[i3]);
    return;
  }
  int i4 = i3 - 256*272;
  if (i4 < 128*144){
    int kap = i4 % 144, n = i4 / 144;
    int part = (kap >= 72);
    int v = kap - (part ? 72 : 0);
    float val = 0.f;
    if (v < 69){
      float mult = (v == 0 || v == 68) ? 1.f : 2.f;
      int a = ((n + 4) * v) % 136;
      float s, c; sincosf((2.f*PI_F/136.f)*(float)a, &s, &c);
      val = part ? (-mult * s) : (mult * c);
    }
    split_bf(val, g_MI2h[i4], g_MI2l[i4]);
  }
}

__global__ void k_H(const float* __restrict__ w, const float* __restrict__ bias){
  int idx = blockIdx.x*blockDim.x + threadIdx.x;
  if (idx >= 64*136*69) return;
  int kw = idx % 69; int t = idx / 69; int kh = t % 136; int c = t / 136;
  float beta = 1.f/(1.f + expf(9.f - bias[c])) + 1e-5f;

  float2 bh[5], bw[5];
  #pragma unroll
  for (int a = 0; a < 5; a++){
    int mh = ((kh*(a-2)) % 272 + 272) % 272;
    float2 th = g_tw[mh]; bh[a] = make_float2(th.x, -th.y);
    int mw = ((kw*(a-2)) % 272 + 272) % 272;
    float2 tw = g_tw[mw]; bw[a] = make_float2(tw.x, -tw.y);
  }
  float2 S0[5], S1[5];
  #pragma unroll
  for (int a = 0; a < 5; a++){
    float2 s0 = make_float2(0.f,0.f), s1 = make_float2(0.f,0.f);
    #pragma unroll
    for (int b = 0; b < 5; b++){
      float wv = w[c*25 + a*5 + b];
      float tx = wv*bw[b].x, ty = wv*bw[b].y;
      s0.x += tx; s0.y += ty;
      if (b & 1){ s1.x -= tx; s1.y -= ty; } else { s1.x += tx; s1.y += ty; }
    }
    S0[a] = s0; S1[a] = s1;
  }
  float2 tph = g_tw[kh];
  float2 ph = make_float2(tph.x, -tph.y);
  float2 tpw = g_tw[kw];
  float2 pw = make_float2(tpw.x, -tpw.y);

  float2 FB[4], G[4];
  float2 Asum = make_float2(0.f,0.f);
  float  invW = 0.f;
  #pragma unroll
  for (int p = 0; p < 2; p++){
    #pragma unroll
    for (int q = 0; q < 2; q++){
      int r = p*2+q;
      float2 fb = make_float2(0.f,0.f);
      #pragma unroll
      for (int a = 0; a < 5; a++){
        float2 S = q ? S1[a] : S0[a];
        float2 term = cmulf(bh[a], S);
        if (p && (a & 1)) { term.x = -term.x; term.y = -term.y; }
        fb.x += term.x; fb.y += term.y;
      }
      FB[r] = fb;
      float2 f1 = make_float2(1.f + (p ? -ph.x : ph.x), (p ? -ph.y : ph.y));
      float2 f2 = make_float2(1.f + (q ? -pw.x : pw.x), (q ? -pw.y : pw.y));
      float2 box = cmulf(f1, f2);
      float2 g = make_float2(fb.x + beta*box.x, -fb.y + beta*box.y);
      G[r] = g;
      float2 ag = cmulf(fb, g);
      Asum.x += ag.x; Asum.y += ag.y;
      invW += fb.x*fb.x + fb.y*fb.y;
    }
  }
  Asum.x *= 0.25f; Asum.y *= 0.25f; invW *= 0.25f;
  float dinv = 1.f/(invW + beta);
  float2 tt = make_float2(Asum.x*dinv, Asum.y*dinv);
  float invb = 1.f/beta;
  float2 Hm[4];
  #pragma unroll
  for (int r = 0; r < 4; r++){
    float2 cf = make_float2(FB[r].x, -FB[r].y);
    float2 ct = cmulf(cf, tt);
    Hm[r] = make_float2((G[r].x - ct.x)*invb, (G[r].y - ct.y)*invb);
  }
  const float scale = 1.f/73984.f;
  float2 twh = make_float2(ph.x, -ph.y);
  float2 tww = make_float2(pw.x, -pw.y);
  #pragma unroll
  for (int rh = 0; rh < 2; rh++){
    #pragma unroll
    for (int rw = 0; rw < 2; rw++){
      float2 s = make_float2(0.f,0.f);
      #pragma unroll
      for (int p = 0; p < 2; p++)
        #pragma unroll
        for (int q = 0; q < 2; q++){
          float sg = ((p*rh + q*rw) & 1) ? -1.f : 1.f;
          s.x += sg*Hm[p*2+q].x; s.y += sg*Hm[p*2+q].y;
        }
      float2 tw = make_float2(1.f, 0.f);
      if (rh) tw = twh;
      if (rw) tw = cmulf(tw, tww);
      float2 o = cmulf(s, tw);
      o.x *= scale; o.y *= scale;
      g_H[((c*4 + rh*2 + rw)*69 + kw)*136 + kh] = o;
    }
  }
}

// ===================== Z = Y .* H, split-bf16, K-major, paired stores =======
__global__ void k_Z(){
  int kw = blockIdx.x;             // [0,69)
  int b  = blockIdx.y;             // [0,256)
  int t  = threadIdx.x;            // [0,68)
  if (t >= 68) return;
  int kh = 2*t;
  int c = b & 63;
  const float* Yr = g_Yt + (b*138 + kw)*136;
  const float* Yi = g_Yt + (b*138 + 69 + kw)*136;
  float yr0 = Yr[kh], yr1 = Yr[kh+1];
  float yi0 = Yi[kh], yi1 = Yi[kh+1];
  #pragma unroll
  for (int r = 0; r < 4; r++){
    const float2* Hp = g_H + ((c*4+r)*69 + kw)*136;
    float2 h0 = Hp[kh], h1 = Hp[kh+1];
    float zr0 = yr0*h0.x - yi0*h0.y, zi0 = yr0*h0.y + yi0*h0.x;
    float zr1 = yr1*h1.x - yi1*h1.y, zi1 = yr1*h1.y + yi1*h1.x;
    int n = r*69 + kw;
    long base = (long)(b*276 + n)*272;
    __nv_bfloat16 ha, la, hb, lb;
    __nv_bfloat162 vh, vl;
    split_bf(zr0, ha, la); split_bf(zr1, hb, lb);
    vh.x = ha; vh.y = hb; vl.x = la; vl.y = lb;
    *reinterpret_cast<__nv_bfloat162*>(g_Zh + base + kh) = vh;
    *reinterpret_cast<__nv_bfloat162*>(g_Zl + base + kh) = vl;
    split_bf(zi0, ha, la); split_bf(zi1, hb, lb);
    vh.x = ha; vh.y = hb; vl.x = la; vl.y = lb;
    *reinterpret_cast<__nv_bfloat162*>(g_Zh + base + 136 + kh) = vh;
    *reinterpret_cast<__nv_bfloat162*>(g_Zl + base + 136 + kh) = vl;
  }
}

// ===================== FFMA2 GEMM stage 0 (symmetry-halved M) ===============
__global__ __launch_bounds__(256, 2) void gemm0_k(const float* __restrict__ xin)
{
  constexpr int K = 128, TC = 16, BM = 128, BN = 128, NT = K/16;
  constexpr int NAQ = BM/64, NBQ = BN/64;

  __shared__ __align__(16) float As[2][16][BM];
  __shared__ __align__(16) float Bs[2][16][BN];

  const int z = blockIdx.z;
  const int tid = threadIdx.x;
  const int tc = tid % TC, tr = tid / TC;
  const int m0 = blockIdx.y*BM;

  auto fetchAq = [&](int rc, int gk)->float4{
    int row;
    if (rc < 69)        row = rc;
    else if (rc < 136)  row = rc + 68;
    else return make_float4(0.f,0.f,0.f,0.f);
    return *reinterpret_cast<const float4*>(g_MB1 + row*128 + gk);
  };
  auto fetchBq = [&](int gk, int gn)->float4{
    return *reinterpret_cast<const float4*>(xin + z*16384 + gk*128 + gn);
  };

  float4 raq[NAQ], rbq[NBQ];
  auto loadAB = [&](int kk){
    #pragma unroll
    for (int i = 0; i < NAQ; i++){
      int e = tid + i*256;
      int m = e >> 2, kq = e & 3;
      raq[i] = fetchAq(m0 + m, kk + kq*4);
    }
    #pragma unroll
    for (int i = 0; i < NBQ; i++){
      int e = tid + i*256;
      int kb = e / (BN/4), nq = e % (BN/4);
      rbq[i] = fetchBq(kk + kb, nq*4);
    }
  };
  auto storeAB = [&](int buf){
    #pragma unroll
    for (int i = 0; i < NAQ; i++){
      int e = tid + i*256;
      int m = e >> 2, kq = e & 3;
      As[buf][kq*4+0][m] = raq[i].x;
      As[buf][kq*4+1][m] = raq[i].y;
      As[buf][kq*4+2][m] = raq[i].z;
      As[buf][kq*4+3][m] = raq[i].w;
    }
    #pragma unroll
    for (int i = 0; i < NBQ; i++){
      int e = tid + i*256;
      int kb = e / (BN/4), nq = e % (BN/4);
      *reinterpret_cast<float4*>(&Bs[buf][kb][nq*4]) = rbq[i];
    }
  };

  unsigned long long acc[4][8] = {};
  loadAB(0); storeAB(0); __syncthreads();

  #pragma unroll 1
  for (int t = 0; t < NT; t++){
    int buf = t & 1;
    if (t + 1 < NT) loadAB((t+1)*16);
    #pragma unroll
    for (int k = 0; k < 16; k++){
      ulonglong2 a01 = *reinterpret_cast<const ulonglong2*>(&As[buf][k][tr*8]);
      ulonglong2 a23 = *reinterpret_cast<const ulonglong2*>(&As[buf][k][tr*8+4]);
      unsigned long long ap[4] = {a01.x, a01.y, a23.x, a23.y};
      float4 b0 = *reinterpret_cast<const float4*>(&Bs[buf][k][tc*8]);
      float4 b1 = *reinterpret_cast<const float4*>(&Bs[buf][k][tc*8+4]);
      unsigned long long bd[8] = {dup2(b0.x),dup2(b0.y),dup2(b0.z),dup2(b0.w),
                                  dup2(b1.x),dup2(b1.y),dup2(b1.z),dup2(b1.w)};
      #pragma unroll
      for (int p = 0; p < 4; p++)
        #pragma unroll
        for (int j = 0; j < 8; j++)
          acc[p][j] = ffma2(ap[p], bd[j], acc[p][j]);
    }
    if (t + 1 < NT){ storeAB(buf ^ 1); __syncthreads(); }
  }

  union { unsigned long long u; float2 f; } pun;
  #pragma unroll
  for (int p = 0; p < 4; p++){
    #pragma unroll
    for (int e = 0; e < 2; e++){
      int rc = m0 + tr*8 + 2*p + e;
      if (rc >= 136) continue;
      bool isTr = (rc < 69);
      int u = isTr ? rc : rc - 68;
      int half = isTr ? 0 : 128;
      __align__(16) __nv_bfloat16 hi[8], lo[8], hin[8], lon[8];
      #pragma unroll
      for (int j = 0; j < 8; j++){
        pun.u = acc[p][j];
        float v = e ? pun.f.y : pun.f.x;
        split_bf(v, hi[j], lo[j]);
        split_bf(-v, hin[j], lon[j]);
      }
      long off = (long)(z*136 + u)*256 + half + tc*8;
      *reinterpret_cast<uint4*>(g_Tbh + off) = *reinterpret_cast<uint4*>(hi);
      *reinterpret_cast<uint4*>(g_Tbl + off) = *reinterpret_cast<uint4*>(lo);
      if (u >= 1 && u <= 67){
        long offm = (long)(z*136 + 136 - u)*256 + half + tc*8;
        if (isTr){
          *reinterpret_cast<uint4*>(g_Tbh + offm) = *reinterpret_cast<uint4*>(hi);
          *reinterpret_cast<uint4*>(g_Tbl + offm) = *reinterpret_cast<uint4*>(lo);
        } else {
          *reinterpret_cast<uint4*>(g_Tbh + offm) = *reinterpret_cast<uint4*>(hin);
          *reinterpret_cast<uint4*>(g_Tbl + offm) = *reinterpret_cast<uint4*>(lon);
        }
      }
      if (isTr && (u == 0 || u == 68)){
        long offz = (long)(z*136 + u)*256 + 128 + tc*8;
        uint4 zz = make_uint4(0u,0u,0u,0u);
        *reinterpret_cast<uint4*>(g_Tbh + offz) = zz;
        *reinterpret_cast<uint4*>(g_Tbl + offz) = zz;
      }
    }
  }
}

// ===================== HMMA split-bf16 GEMM, 4x2 warp grid, 1 sync/chunk ====
// STAGE 1: Yt = Tsp(34816x256) * MB2t(144x256)^T  -> g_Yt (fp32, transposed)
// STAGE 2: U(256x276) = MI1(256x272) * Z_b(276x272)^T -> g_UA split bf16
// STAGE 3: out = UA_z(128x144) * MI2(128x144)^T -> d_out interleaved
template<int STAGE>
__global__ __launch_bounds__(256) void mma_k(float* __restrict__ outp)
{
  constexpr int BN  = (STAGE==3) ? 128 : 96;
  constexpr int K   = (STAGE==1) ? 256 : (STAGE==2) ? 272 : 144;
  constexpr int KC  = 32;
  constexpr int NCH = (K + KC - 1)/KC;
  constexpr int SAB = 80;
  constexpr int WN  = BN/2;        // 48 or 64
  constexpr int NJ  = WN/8;        // 6 or 8
  constexpr int ABY = 128*SAB;
  constexpr int BBY = BN*SAB;
  constexpr int OAH = 0, OAL = ABY, OBH = 2*ABY, OBL = 2*ABY + BBY;
  constexpr int BUFB = 2*ABY + 2*BBY;

  extern __shared__ __align__(16) char smraw[];

  const int tid = threadIdx.x, lane = tid & 31, wid = tid >> 5;
  const int wm = wid & 3, wn = wid >> 2;

  int b = 0, n0 = 0, z = 0, mt = 0;
  const __nv_bfloat16 *Ahs, *Als, *Bhs, *Bls;
  if constexpr (STAGE==1){
    mt = blockIdx.y; n0 = blockIdx.x*96;
    Ahs = g_Tbh + (long)mt*128*256; Als = g_Tbl + (long)mt*128*256;
    Bhs = g_MB2th; Bls = g_MB2tl;
  } else if constexpr (STAGE==2){
    b = blockIdx.z; mt = blockIdx.y; n0 = blockIdx.x*96;
    Ahs = g_MI1h + mt*128*272; Als = g_MI1l + mt*128*272;
    Bhs = g_Zh + (long)b*276*272; Bls = g_Zl + (long)b*276*272;
  } else {
    z = blockIdx.x;
    Ahs = g_UAh + (long)z*128*144; Als = g_UAl + (long)z*128*144;
    Bhs = g_MI2h; Bls = g_MI2l;
  }

  auto issue = [&](int t, int buf){
    const int kk = t*KC;
    char* base = smraw + buf*BUFB;
    #pragma unroll
    for (int it = 0; it < 4; it++){
      int cid = tid + it*256;
      int hl = cid >> 9, rem = cid & 511;
      int row = rem >> 2, c16 = rem & 3;
      int gk = kk + c16*8;
      int sz = (gk + 8 <= K) ? 16 : 0;
      const __nv_bfloat16* src = (hl ? Als : Ahs) + (long)row*K + (sz ? gk : 0);
      uint32_t dst = smem_u32(base + (hl ? OAL : OAH) + row*SAB + c16*16);
      asm volatile("cp.async.ca.shared.global [%0], [%1], 16, %2;"
                   :: "r"(dst), "l"(src), "r"(sz));
    }
    constexpr int BCH = BN*8;
    #pragma unroll
    for (int it = 0; it < BCH/256; it++){
      int cid = tid + it*256;
      int hl = (cid >= BCH/2), rem = cid % (BCH/2);
      int row = rem >> 2, c16 = rem & 3;
      int gk = kk + c16*8;
      int grow = row;
      int sz = (gk + 8 <= K) ? 16 : 0;
      if constexpr (STAGE==1){
        grow = n0 + row;
        if (grow >= 144){ grow = 143; sz = 0; }
      }
      if constexpr (STAGE==2){
        grow = n0 + row;
        if (grow >= 276){ grow = 275; sz = 0; }
      }
      const __nv_bfloat16* src = (hl ? Bls : Bhs) + (long)grow*K + (sz ? gk : 0);
      uint32_t dst = smem_u32(base + (hl ? OBL : OBH) + row*SAB + c16*16);
      asm volatile("cp.async.ca.shared.global [%0], [%1], 16, %2;"
                   :: "r"(dst), "l"(src), "r"(sz));
    }
    asm volatile("cp.async.commit_group;" ::: "memory");
  };

  float acc[2][NJ][4];
  #pragma unroll
  for (int i = 0; i < 2; i++)
    #pragma unroll
    for (int j = 0; j < NJ; j++)
      #pragma unroll
      for (int q = 0; q < 4; q++) acc[i][j][q] = 0.f;

  issue(0, 0);

  // single sync per chunk: wait -> sync -> issue(t+1 into freed buffer) -> compute
  #pragma unroll 1
  for (int t = 0; t < NCH; t++){
    const int buf = t & 1;
    asm volatile("cp.async.wait_group 0;" ::: "memory");
    __syncthreads();
    if (t + 1 < NCH) issue(t + 1, buf ^ 1);

    char* base = smraw + buf*BUFB;
    const int nsub = (K - t*KC >= KC) ? 2 : 1;
    #pragma unroll
    for (int sub = 0; sub < 2; sub++){
      if (sub >= nsub) break;
      const int tk = sub*16;
      uint32_t afh[2][4], afl[2][4];
      #pragma unroll
      for (int i = 0; i < 2; i++){
        int row = wm*32 + i*16 + (lane & 15);
        int col = tk + (lane >> 4)*8;
        ldsm_x4(afh[i][0], afh[i][1], afh[i][2], afh[i][3],
                smem_u32(base + OAH + row*SAB + col*2));
        ldsm_x4(afl[i][0], afl[i][1], afl[i][2], afl[i][3],
                smem_u32(base + OAL + row*SAB + col*2));
      }
      uint32_t bfh[NJ][2], bfl[NJ][2];
      #pragma unroll
      for (int j0 = 0; j0 < NJ; j0 += 2){
        int q = lane >> 3;
        int row = wn*WN + (j0 + (q >> 1))*8 + (lane & 7);
        int col = tk + (q & 1)*8;
        ldsm_x4(bfh[j0][0], bfh[j0][1], bfh[j0+1][0], bfh[j0+1][1],
                smem_u32(base + OBH + row*SAB + col*2));
        ldsm_x4(bfl[j0][0], bfl[j0][1], bfl[j0+1][0], bfl[j0+1][1],
                smem_u32(base + OBL + row*SAB + col*2));
      }
      #pragma unroll
      for (int i = 0; i < 2; i++)
        #pragma unroll
        for (int j = 0; j < NJ; j++){
          mma_bf16(acc[i][j], afh[i], bfh[j]);
          mma_bf16(acc[i][j], afh[i], bfl[j]);
          mma_bf16(acc[i][j], afl[i], bfh[j]);
        }
    }
  }
  __syncthreads();   // retire last compute before reusing smem for epilogue

  // ---- single-pass coalesced epilogue via SMEM staging
  float* S = reinterpret_cast<float*>(smraw);  // BN x 129 floats
  const int g = lane >> 2, tig = lane & 3;

  #pragma unroll
  for (int i = 0; i < 2; i++)
    #pragma unroll
    for (int j = 0; j < NJ; j++)
      #pragma unroll
      for (int h = 0; h < 2; h++)
        #pragma unroll
        for (int e = 0; e < 2; e++){
          int row = wm*32 + i*16 + g + h*8;
          int lc  = wn*WN + j*8 + tig*2 + e;
          S[lc*129 + row] = acc[i][j][h*2 + e];
        }
  __syncthreads();

  for (int idx = tid; idx < BN*128; idx += 256){
    if constexpr (STAGE==1){
      int m = idx & 127, cc = idx >> 7;     // m-fast: coalesced g_Yt stores
      int gn = n0 + cc;
      if (gn < 138){
        int gmm = mt*128 + m;
        int bb = gmm / 136, uu = gmm - bb*136;
        g_Yt[((long)bb*138 + gn)*136 + uu] = S[cc*129 + m];
      }
    } else if constexpr (STAGE==2){
      int m = idx / BN, cc = idx % BN;
      int gc = n0 + cc;
      if (gc < 276){
        int r = gc/69, v = gc - r*69;
        long dst = (long)((b*4 + r)*128 + m)*144 + mt*72 + v;
        split_bf(S[cc*129 + m], g_UAh[dst], g_UAl[dst]);
      }
    } else {
      int m = idx / BN, gc = idx % BN;
      int rr = z & 3, bb = z >> 2;
      outp[(long)bb*65536 + (2*m + (rr >> 1))*256 + 2*gc + (rr & 1)] = S[gc*129 + m];
    }
  }
}

// ===================== launch ===============================================
extern "C" void kernel_launch(void* const* d_in, const int* in_sizes, int n_in,
                              void* d_out, int out_size)
{
  const float* x = (const float*)d_in[0];
  const float* w = (const float*)(n_in > 1 ? d_in[1] : d_in[0]);
  const float* bias = (const float*)(n_in > 2 ? d_in[2] : d_in[0]);
  for (int i = 0; i < n_in; i++){
    if (in_sizes[i] == 4*64*128*128) x = (const float*)d_in[i];
    else if (in_sizes[i] == 64*25)   w = (const float*)d_in[i];
    else if (in_sizes[i] == 64)      bias = (const float*)d_in[i];
  }
  float* out = (float*)d_out;

  constexpr int SM96  = 2*(2*128*80 + 2*96*80);    // 71680 (stages 1,2)
  constexpr int SM128 = 2*(2*128*80 + 2*128*80);   // 81920 (stage 3)
  cudaFuncSetAttribute(mma_k<1>, cudaFuncAttributeMaxDynamicSharedMemorySize, SM96);
  cudaFuncSetAttribute(mma_k<2>, cudaFuncAttributeMaxDynamicSharedMemorySize, SM96);
  cudaFuncSetAttribute(mma_k<3>, cudaFuncAttributeMaxDynamicSharedMemorySize, SM128);

  k_build<<<(160016+255)/256, 256>>>();            // #1
  k_H   <<<(64*136*69+255)/256, 256>>>(w, bias);   // #2
  gemm0_k<<<dim3(1,2,256), 256>>>(x);              // #3: Tsp (symmetry-halved)
  mma_k<1><<<dim3(2,272,1), 256, SM96>>>(out);     // #4: Yt = Tsp * MB2t^T
  k_Z   <<<dim3(69,256), 68>>>();                  // #5: Z = Y .* H (paired)
  mma_k<2><<<dim3(3,2,256), 256, SM96>>>(out);     // #6: U -> g_UA (profiled)
  mma_k<3><<<dim3(1024,1,1), 256, SM128>>>(out);   // #7: out
}

// round 16
// speedup vs baseline: 1.0081x; 1.0081x over previous
#include <cuda_runtime.h>
#include <cuda_bf16.h>
#include <math.h>
#include <cstdint>

#define PI_F 3.14159265358979323846f

// ===================== helpers ==============================================
__device__ __forceinline__ uint32_t smem_u32(const void* p){
  uint32_t a;
  asm("{ .reg .u64 t; cvta.to.shared.u64 t, %1; cvt.u32.u64 %0, t; }"
      : "=r"(a) : "l"(p));
  return a;
}
__device__ __forceinline__ void ldsm_x4(uint32_t &r0, uint32_t &r1,
                                        uint32_t &r2, uint32_t &r3, uint32_t addr){
  asm volatile("ldmatrix.sync.aligned.m8n8.x4.shared.b16 {%0,%1,%2,%3}, [%4];"
               : "=r"(r0), "=r"(r1), "=r"(r2), "=r"(r3) : "r"(addr));
}
__device__ __forceinline__ void mma_bf16(float d[4], const uint32_t a[4],
                                         const uint32_t b[2]){
  asm volatile("mma.sync.aligned.m16n8k16.row.col.f32.bf16.bf16.f32 "
    "{%0,%1,%2,%3}, {%4,%5,%6,%7}, {%8,%9}, {%0,%1,%2,%3};"
    : "+f"(d[0]), "+f"(d[1]), "+f"(d[2]), "+f"(d[3])
    : "r"(a[0]), "r"(a[1]), "r"(a[2]), "r"(a[3]), "r"(b[0]), "r"(b[1]));
}
__device__ __forceinline__ unsigned long long ffma2(unsigned long long a,
                                                    unsigned long long b,
                                                    unsigned long long c){
  unsigned long long d;
  asm("fma.rn.f32x2 %0, %1, %2, %3;" : "=l"(d) : "l"(a), "l"(b), "l"(c));
  return d;
}
__device__ __forceinline__ unsigned long long dup2(float v){
  unsigned long long d; unsigned int u = __float_as_uint(v);
  asm("mov.b64 %0, {%1, %1};" : "=l"(d) : "r"(u));
  return d;
}
__device__ __forceinline__ float2 cmulf(float2 a, float2 b){
  return make_float2(a.x*b.x - a.y*b.y, a.x*b.y + a.y*b.x);
}
__device__ __forceinline__ void split_bf(float f, __nv_bfloat16 &h, __nv_bfloat16 &l){
  h = __float2bfloat16(f);
  l = __float2bfloat16(f - __bfloat162float(h));
}
__device__ __forceinline__ void fold_cs(int u, int ip, float &sumc, float &sumns){
  sumc = 0.f; sumns = 0.f;
  int iv[3]; int n = 0;
  iv[n++] = ip + 4;
  if (ip >= 124) iv[n++] = ip - 124;
  if (ip <= 3)   iv[n++] = ip + 132;
  for (int t = 0; t < n; t++){
    int m = (u * iv[t]) % 136;
    float s, c;
    sincosf((2.f*PI_F/136.f) * (float)m, &s, &c);
    sumc += c; sumns -= s;
  }
}

// ===================== persistent scratch ===================================
static __device__ __align__(16) __nv_bfloat16 g_Tbh[256*136*256]; // Tsp hi
static __device__ __align__(16) __nv_bfloat16 g_Tbl[256*136*256]; // Tsp lo
static __device__ float  g_Yt[256*138*136];                 // [b][n 138][u 136]
static __device__ float2 g_H [64*4*69*136];                 // [c][r][kw][kh]
static __device__ __align__(16) __nv_bfloat16 g_Zh[256*276*272];
static __device__ __align__(16) __nv_bfloat16 g_Zl[256*276*272];
static __device__ __align__(16) __nv_bfloat16 g_UAh[1024*128*144];
static __device__ __align__(16) __nv_bfloat16 g_UAl[1024*128*144];
static __device__ float  g_MB1[272*128];
static __device__ __align__(16) __nv_bfloat16 g_MB2th[144*256];  // MB2^T split
static __device__ __align__(16) __nv_bfloat16 g_MB2tl[144*256];
static __device__ __align__(16) __nv_bfloat16 g_MI1h[256*272];
static __device__ __align__(16) __nv_bfloat16 g_MI1l[256*272];
static __device__ __align__(16) __nv_bfloat16 g_MI2h[128*144];
static __device__ __align__(16) __nv_bfloat16 g_MI2l[128*144];
static __device__ float2 g_tw[272];

// ===================== merged builder =======================================
__global__ void k_build(){
  int idx = blockIdx.x*blockDim.x + threadIdx.x;
  if (idx < 272){
    float s, c; sincosf((2.f*PI_F/272.f)*(float)idx, &s, &c);
    g_tw[idx] = make_float2(c, s);
    return;
  }
  int i1 = idx - 272;
  if (i1 < 272*128){
    int col = i1 % 128, row = i1 / 128;
    int u = (row < 136) ? row : row - 136;
    float sc, sn; fold_cs(u, col, sc, sn);
    g_MB1[i1] = (row < 136) ? sc : sn;
    return;
  }
  int i2 = i1 - 272*128;
  if (i2 < 144*256){                       // MB2^T split: [n][k]
    int k = i2 % 256, n = i2 / 256;
    float val = 0.f;
    if (n < 138){
      int v  = (n < 69) ? n : n - 69;
      int jp = (k < 128) ? k : k - 128;
      float sc, sn; fold_cs(v, jp, sc, sn);
      if (n < 69) val = (k < 128) ? sc : -sn;
      else        val = (k < 128) ? sn :  sc;
    }
    split_bf(val, g_MB2th[i2], g_MB2tl[i2]);
    return;
  }
  int i3 = i2 - 144*256;
  if (i3 < 256*272){
    int k = i3 % 272, row = i3 / 272;
    int m   = (row & 127) + 4;
    int kap = (k < 136) ? k : k - 136;
    int a = (m * kap) % 136;
    float s, c; sincosf((2.f*PI_F/136.f)*(float)a, &s, &c);
    float val;
    if (row < 128) val = (k < 136) ?  c : -s;
    else           val = (k < 136) ?  s :  c;
    split_bf(val, g_MI1h[i3], g_MI1l[i3]);
    return;
  }
  int i4 = i3 - 256*272;
  if (i4 < 128*144){
    int kap = i4 % 144, n = i4 / 144;
    int part = (kap >= 72);
    int v = kap - (part ? 72 : 0);
    float val = 0.f;
    if (v < 69){
      float mult = (v == 0 || v == 68) ? 1.f : 2.f;
      int a = ((n + 4) * v) % 136;
      float s, c; sincosf((2.f*PI_F/136.f)*(float)a, &s, &c);
      val = part ? (-mult * s) : (mult * c);
    }
    split_bf(val, g_MI2h[i4], g_MI2l[i4]);
  }
}

__global__ void k_H(const float* __restrict__ w, const float* __restrict__ bias){
  int idx = blockIdx.x*blockDim.x + threadIdx.x;
  if (idx >= 64*136*69) return;
  int kw = idx % 69; int t = idx / 69; int kh = t % 136; int c = t / 136;
  float beta = 1.f/(1.f + expf(9.f - bias[c])) + 1e-5f;

  float2 bh[5], bw[5];
  #pragma unroll
  for (int a = 0; a < 5; a++){
    int mh = ((kh*(a-2)) % 272 + 272) % 272;
    float2 th = g_tw[mh]; bh[a] = make_float2(th.x, -th.y);
    int mw = ((kw*(a-2)) % 272 + 272) % 272;
    float2 tw = g_tw[mw]; bw[a] = make_float2(tw.x, -tw.y);
  }
  float2 S0[5], S1[5];
  #pragma unroll
  for (int a = 0; a < 5; a++){
    float2 s0 = make_float2(0.f,0.f), s1 = make_float2(0.f,0.f);
    #pragma unroll
    for (int b = 0; b < 5; b++){
      float wv = w[c*25 + a*5 + b];
      float tx = wv*bw[b].x, ty = wv*bw[b].y;
      s0.x += tx; s0.y += ty;
      if (b & 1){ s1.x -= tx; s1.y -= ty; } else { s1.x += tx; s1.y += ty; }
    }
    S0[a] = s0; S1[a] = s1;
  }
  float2 tph = g_tw[kh];
  float2 ph = make_float2(tph.x, -tph.y);
  float2 tpw = g_tw[kw];
  float2 pw = make_float2(tpw.x, -tpw.y);

  float2 FB[4], G[4];
  float2 Asum = make_float2(0.f,0.f);
  float  invW = 0.f;
  #pragma unroll
  for (int p = 0; p < 2; p++){
    #pragma unroll
    for (int q = 0; q < 2; q++){
      int r = p*2+q;
      float2 fb = make_float2(0.f,0.f);
      #pragma unroll
      for (int a = 0; a < 5; a++){
        float2 S = q ? S1[a] : S0[a];
        float2 term = cmulf(bh[a], S);
        if (p && (a & 1)) { term.x = -term.x; term.y = -term.y; }
        fb.x += term.x; fb.y += term.y;
      }
      FB[r] = fb;
      float2 f1 = make_float2(1.f + (p ? -ph.x : ph.x), (p ? -ph.y : ph.y));
      float2 f2 = make_float2(1.f + (q ? -pw.x : pw.x), (q ? -pw.y : pw.y));
      float2 box = cmulf(f1, f2);
      float2 g = make_float2(fb.x + beta*box.x, -fb.y + beta*box.y);
      G[r] = g;
      float2 ag = cmulf(fb, g);
      Asum.x += ag.x; Asum.y += ag.y;
      invW += fb.x*fb.x + fb.y*fb.y;
    }
  }
  Asum.x *= 0.25f; Asum.y *= 0.25f; invW *= 0.25f;
  float dinv = 1.f/(invW + beta);
  float2 tt = make_float2(Asum.x*dinv, Asum.y*dinv);
  float invb = 1.f/beta;
  float2 Hm[4];
  #pragma unroll
  for (int r = 0; r < 4; r++){
    float2 cf = make_float2(FB[r].x, -FB[r].y);
    float2 ct = cmulf(cf, tt);
    Hm[r] = make_float2((G[r].x - ct.x)*invb, (G[r].y - ct.y)*invb);
  }
  const float scale = 1.f/73984.f;
  float2 twh = make_float2(ph.x, -ph.y);
  float2 tww = make_float2(pw.x, -pw.y);
  #pragma unroll
  for (int rh = 0; rh < 2; rh++){
    #pragma unroll
    for (int rw = 0; rw < 2; rw++){
      float2 s = make_float2(0.f,0.f);
      #pragma unroll
      for (int p = 0; p < 2; p++)
        #pragma unroll
        for (int q = 0; q < 2; q++){
          float sg = ((p*rh + q*rw) & 1) ? -1.f : 1.f;
          s.x += sg*Hm[p*2+q].x; s.y += sg*Hm[p*2+q].y;
        }
      float2 tw = make_float2(1.f, 0.f);
      if (rh) tw = twh;
      if (rw) tw = cmulf(tw, tww);
      float2 o = cmulf(s, tw);
      o.x *= scale; o.y *= scale;
      g_H[((c*4 + rh*2 + rw)*69 + kw)*136 + kh] = o;
    }
  }
}

// ===================== Z = Y .* H, split-bf16, paired stores, flat grid =====
__global__ void k_Z(){
  int idx = blockIdx.x*blockDim.x + threadIdx.x;
  if (idx >= 256*69*68) return;
  int t  = idx % 68;
  int r2 = idx / 68;
  int kw = r2 % 69;
  int b  = r2 / 69;
  int kh = 2*t;
  int c = b & 63;
  const float* Yr = g_Yt + (b*138 + kw)*136;
  const float* Yi = g_Yt + (b*138 + 69 + kw)*136;
  float yr0 = Yr[kh], yr1 = Yr[kh+1];
  float yi0 = Yi[kh], yi1 = Yi[kh+1];
  #pragma unroll
  for (int r = 0; r < 4; r++){
    const float2* Hp = g_H + ((c*4+r)*69 + kw)*136;
    float2 h0 = Hp[kh], h1 = Hp[kh+1];
    float zr0 = yr0*h0.x - yi0*h0.y, zi0 = yr0*h0.y + yi0*h0.x;
    float zr1 = yr1*h1.x - yi1*h1.y, zi1 = yr1*h1.y + yi1*h1.x;
    int n = r*69 + kw;
    long base = (long)(b*276 + n)*272;
    __nv_bfloat16 ha, la, hb, lb;
    __nv_bfloat162 vh, vl;
    split_bf(zr0, ha, la); split_bf(zr1, hb, lb);
    vh.x = ha; vh.y = hb; vl.x = la; vl.y = lb;
    *reinterpret_cast<__nv_bfloat162*>(g_Zh + base + kh) = vh;
    *reinterpret_cast<__nv_bfloat162*>(g_Zl + base + kh) = vl;
    split_bf(zi0, ha, la); split_bf(zi1, hb, lb);
    vh.x = ha; vh.y = hb; vl.x = la; vl.y = lb;
    *reinterpret_cast<__nv_bfloat162*>(g_Zh + base + 136 + kh) = vh;
    *reinterpret_cast<__nv_bfloat162*>(g_Zl + base + 136 + kh) = vl;
  }
}

// ===================== FFMA2 GEMM stage 0 (symmetry-halved M) ===============
__global__ __launch_bounds__(256, 2) void gemm0_k(const float* __restrict__ xin)
{
  constexpr int K = 128, TC = 16, BM = 128, BN = 128, NT = K/16;
  constexpr int NAQ = BM/64, NBQ = BN/64;

  __shared__ __align__(16) float As[2][16][BM];
  __shared__ __align__(16) float Bs[2][16][BN];

  const int z = blockIdx.z;
  const int tid = threadIdx.x;
  const int tc = tid % TC, tr = tid / TC;
  const int m0 = blockIdx.y*BM;

  auto fetchAq = [&](int rc, int gk)->float4{
    int row;
    if (rc < 69)        row = rc;
    else if (rc < 136)  row = rc + 68;
    else return make_float4(0.f,0.f,0.f,0.f);
    return *reinterpret_cast<const float4*>(g_MB1 + row*128 + gk);
  };
  auto fetchBq = [&](int gk, int gn)->float4{
    return *reinterpret_cast<const float4*>(xin + z*16384 + gk*128 + gn);
  };

  float4 raq[NAQ], rbq[NBQ];
  auto loadAB = [&](int kk){
    #pragma unroll
    for (int i = 0; i < NAQ; i++){
      int e = tid + i*256;
      int m = e >> 2, kq = e & 3;
      raq[i] = fetchAq(m0 + m, kk + kq*4);
    }
    #pragma unroll
    for (int i = 0; i < NBQ; i++){
      int e = tid + i*256;
      int kb = e / (BN/4), nq = e % (BN/4);
      rbq[i] = fetchBq(kk + kb, nq*4);
    }
  };
  auto storeAB = [&](int buf){
    #pragma unroll
    for (int i = 0; i < NAQ; i++){
      int e = tid + i*256;
      int m = e >> 2, kq = e & 3;
      As[buf][kq*4+0][m] = raq[i].x;
      As[buf][kq*4+1][m] = raq[i].y;
      As[buf][kq*4+2][m] = raq[i].z;
      As[buf][kq*4+3][m] = raq[i].w;
    }
    #pragma unroll
    for (int i = 0; i < NBQ; i++){
      int e = tid + i*256;
      int kb = e / (BN/4), nq = e % (BN/4);
      *reinterpret_cast<float4*>(&Bs[buf][kb][nq*4]) = rbq[i];
    }
  };

  unsigned long long acc[4][8] = {};
  loadAB(0); storeAB(0); __syncthreads();

  #pragma unroll 1
  for (int t = 0; t < NT; t++){
    int buf = t & 1;
    if (t + 1 < NT) loadAB((t+1)*16);
    #pragma unroll
    for (int k = 0; k < 16; k++){
      ulonglong2 a01 = *reinterpret_cast<const ulonglong2*>(&As[buf][k][tr*8]);
      ulonglong2 a23 = *reinterpret_cast<const ulonglong2*>(&As[buf][k][tr*8+4]);
      unsigned long long ap[4] = {a01.x, a01.y, a23.x, a23.y};
      float4 b0 = *reinterpret_cast<const float4*>(&Bs[buf][k][tc*8]);
      float4 b1 = *reinterpret_cast<const float4*>(&Bs[buf][k][tc*8+4]);
      unsigned long long bd[8] = {dup2(b0.x),dup2(b0.y),dup2(b0.z),dup2(b0.w),
                                  dup2(b1.x),dup2(b1.y),dup2(b1.z),dup2(b1.w)};
      #pragma unroll
      for (int p = 0; p < 4; p++)
        #pragma unroll
        for (int j = 0; j < 8; j++)
          acc[p][j] = ffma2(ap[p], bd[j], acc[p][j]);
    }
    if (t + 1 < NT){ storeAB(buf ^ 1); __syncthreads(); }
  }

  union { unsigned long long u; float2 f; } pun;
  #pragma unroll
  for (int p = 0; p < 4; p++){
    #pragma unroll
    for (int e = 0; e < 2; e++){
      int rc = m0 + tr*8 + 2*p + e;
      if (rc >= 136) continue;
      bool isTr = (rc < 69);
      int u = isTr ? rc : rc - 68;
      int half = isTr ? 0 : 128;
      __align__(16) __nv_bfloat16 hi[8], lo[8], hin[8], lon[8];
      #pragma unroll
      for (int j = 0; j < 8; j++){
        pun.u = acc[p][j];
        float v = e ? pun.f.y : pun.f.x;
        split_bf(v, hi[j], lo[j]);
        split_bf(-v, hin[j], lon[j]);
      }
      long off = (long)(z*136 + u)*256 + half + tc*8;
      *reinterpret_cast<uint4*>(g_Tbh + off) = *reinterpret_cast<uint4*>(hi);
      *reinterpret_cast<uint4*>(g_Tbl + off) = *reinterpret_cast<uint4*>(lo);
      if (u >= 1 && u <= 67){
        long offm = (long)(z*136 + 136 - u)*256 + half + tc*8;
        if (isTr){
          *reinterpret_cast<uint4*>(g_Tbh + offm) = *reinterpret_cast<uint4*>(hi);
          *reinterpret_cast<uint4*>(g_Tbl + offm) = *reinterpret_cast<uint4*>(lo);
        } else {
          *reinterpret_cast<uint4*>(g_Tbh + offm) = *reinterpret_cast<uint4*>(hin);
          *reinterpret_cast<uint4*>(g_Tbl + offm) = *reinterpret_cast<uint4*>(lon);
        }
      }
      if (isTr && (u == 0 || u == 68)){
        long offz = (long)(z*136 + u)*256 + 128 + tc*8;
        uint4 zz = make_uint4(0u,0u,0u,0u);
        *reinterpret_cast<uint4*>(g_Tbh + offz) = zz;
        *reinterpret_cast<uint4*>(g_Tbl + offz) = zz;
      }
    }
  }
}

// ===================== HMMA split-bf16 GEMM, 4x2 warp grid ==================
// STAGE 1: Yt = Tsp(34816x256) * MB2t(144x256)^T  -> g_Yt (fp32, transposed)
// STAGE 2: U(256x276) = MI1(256x272) * Z_b(276x272)^T -> g_UA split bf16
// STAGE 3: out = UA_z(128x144) * MI2(128x144)^T -> d_out interleaved
template<int STAGE>
__global__ __launch_bounds__(256) void mma_k(float* __restrict__ outp)
{
  constexpr int BN  = (STAGE==3) ? 128 : 96;
  constexpr int K   = (STAGE==1) ? 256 : (STAGE==2) ? 272 : 144;
  constexpr int KC  = 32;
  constexpr int NCH = (K + KC - 1)/KC;
  constexpr int SAB = 80;
  constexpr int WN  = BN/2;        // 48 or 64
  constexpr int NJ  = WN/8;        // 6 or 8
  constexpr int ABY = 128*SAB;
  constexpr int BBY = BN*SAB;
  constexpr int OAH = 0, OAL = ABY, OBH = 2*ABY, OBL = 2*ABY + BBY;
  constexpr int BUFB = 2*ABY + 2*BBY;

  extern __shared__ __align__(16) char smraw[];

  const int tid = threadIdx.x, lane = tid & 31, wid = tid >> 5;
  const int wm = wid & 3, wn = wid >> 2;

  int b = 0, n0 = 0, z = 0, mt = 0;
  const __nv_bfloat16 *Ahs, *Als, *Bhs, *Bls;
  if constexpr (STAGE==1){
    mt = blockIdx.y; n0 = blockIdx.x*96;
    Ahs = g_Tbh + (long)mt*128*256; Als = g_Tbl + (long)mt*128*256;
    Bhs = g_MB2th; Bls = g_MB2tl;
  } else if constexpr (STAGE==2){
    b = blockIdx.z; mt = blockIdx.y; n0 = blockIdx.x*96;
    Ahs = g_MI1h + mt*128*272; Als = g_MI1l + mt*128*272;
    Bhs = g_Zh + (long)b*276*272; Bls = g_Zl + (long)b*276*272;
  } else {
    z = blockIdx.x;
    Ahs = g_UAh + (long)z*128*144; Als = g_UAl + (long)z*128*144;
    Bhs = g_MI2h; Bls = g_MI2l;
  }

  auto issue = [&](int t, int buf){
    const int kk = t*KC;
    char* base = smraw + buf*BUFB;
    #pragma unroll
    for (int it = 0; it < 4; it++){
      int cid = tid + it*256;
      int hl = cid >> 9, rem = cid & 511;
      int row = rem >> 2, c16 = rem & 3;
      int gk = kk + c16*8;
      int sz = (gk + 8 <= K) ? 16 : 0;
      const __nv_bfloat16* src = (hl ? Als : Ahs) + (long)row*K + (sz ? gk : 0);
      uint32_t dst = smem_u32(base + (hl ? OAL : OAH) + row*SAB + c16*16);
      asm volatile("cp.async.ca.shared.global [%0], [%1], 16, %2;"
                   :: "r"(dst), "l"(src), "r"(sz));
    }
    constexpr int BCH = BN*8;
    #pragma unroll
    for (int it = 0; it < BCH/256; it++){
      int cid = tid + it*256;
      int hl = (cid >= BCH/2), rem = cid % (BCH/2);
      int row = rem >> 2, c16 = rem & 3;
      int gk = kk + c16*8;
      int grow = row;
      int sz = (gk + 8 <= K) ? 16 : 0;
      if constexpr (STAGE==1){
        grow = n0 + row;
        if (grow >= 144){ grow = 143; sz = 0; }
      }
      if constexpr (STAGE==2){
        grow = n0 + row;
        if (grow >= 276){ grow = 275; sz = 0; }
      }
      const __nv_bfloat16* src = (hl ? Bls : Bhs) + (long)grow*K + (sz ? gk : 0);
      uint32_t dst = smem_u32(base + (hl ? OBL : OBH) + row*SAB + c16*16);
      asm volatile("cp.async.ca.shared.global [%0], [%1], 16, %2;"
                   :: "r"(dst), "l"(src), "r"(sz));
    }
    asm volatile("cp.async.commit_group;" ::: "memory");
  };

  float acc[2][NJ][4];
  #pragma unroll
  for (int i = 0; i < 2; i++)
    #pragma unroll
    for (int j = 0; j < NJ; j++)
      #pragma unroll
      for (int q = 0; q < 4; q++) acc[i][j][q] = 0.f;

  issue(0, 0);

  #pragma unroll 1
  for (int t = 0; t < NCH; t++){
    const int buf = t & 1;
    if (t + 1 < NCH){
      issue(t + 1, buf ^ 1);
      asm volatile("cp.async.wait_group 1;" ::: "memory");
    } else {
      asm volatile("cp.async.wait_group 0;" ::: "memory");
    }
    __syncthreads();

    char* base = smraw + buf*BUFB;
    const int nsub = (K - t*KC >= KC) ? 2 : 1;
    #pragma unroll
    for (int sub = 0; sub < 2; sub++){
      if (sub >= nsub) break;
      const int tk = sub*16;
      uint32_t afh[2][4], afl[2][4];
      #pragma unroll
      for (int i = 0; i < 2; i++){
        int row = wm*32 + i*16 + (lane & 15);
        int col = tk + (lane >> 4)*8;
        ldsm_x4(afh[i][0], afh[i][1], afh[i][2], afh[i][3],
                smem_u32(base + OAH + row*SAB + col*2));
        ldsm_x4(afl[i][0], afl[i][1], afl[i][2], afl[i][3],
                smem_u32(base + OAL + row*SAB + col*2));
      }
      uint32_t bfh[NJ][2], bfl[NJ][2];
      #pragma unroll
      for (int j0 = 0; j0 < NJ; j0 += 2){
        int q = lane >> 3;
        int row = wn*WN + (j0 + (q >> 1))*8 + (lane & 7);
        int col = tk + (q & 1)*8;
        ldsm_x4(bfh[j0][0], bfh[j0][1], bfh[j0+1][0], bfh[j0+1][1],
                smem_u32(base + OBH + row*SAB + col*2));
        ldsm_x4(bfl[j0][0], bfl[j0][1], bfl[j0+1][0], bfl[j0+1][1],
                smem_u32(base + OBL + row*SAB + col*2));
      }
      #pragma unroll
      for (int i = 0; i < 2; i++)
        #pragma unroll
        for (int j = 0; j < NJ; j++){
          mma_bf16(acc[i][j], afh[i], bfh[j]);
          mma_bf16(acc[i][j], afh[i], bfl[j]);
          mma_bf16(acc[i][j], afl[i], bfh[j]);
        }
    }
    __syncthreads();
  }

  // ---- coalesced epilogue via SMEM staging (one pass per N-warp group)
  float* S = reinterpret_cast<float*>(smraw);
  const int g = lane >> 2, tig = lane & 3;
  constexpr int CG = WN;

  #pragma unroll 1
  for (int p = 0; p < 2; p++){
    if (wn == p){
      #pragma unroll
      for (int i = 0; i < 2; i++)
        #pragma unroll
        for (int j = 0; j < NJ; j++)
          #pragma unroll
          for (int h = 0; h < 2; h++)
            #pragma unroll
            for (int e = 0; e < 2; e++){
              int row = wm*32 + i*16 + g + h*8;
              int lc  = j*8 + tig*2 + e;
              S[lc*129 + row] = acc[i][j][h*2 + e];
            }
    }
    __syncthreads();
    for (int idx = tid; idx < CG*128; idx += 256){
      if constexpr (STAGE==1){
        int m = idx & 127, cc = idx >> 7;     // m-fast: coalesced g_Yt stores
        int gn = n0 + p*CG + cc;
        if (gn < 138){
          int gmm = mt*128 + m;
          int bb = gmm / 136, uu = gmm - bb*136;
          g_Yt[((long)bb*138 + gn)*136 + uu] = S[cc*129 + m];
        }
      } else {
        int m = idx / CG, cc = idx % CG;
        float val = S[cc*129 + m];
        if constexpr (STAGE==2){
          int gc = n0 + p*CG + cc;
          if (gc < 276){
            int r = gc/69, v = gc - r*69;
            long dst = (long)((b*4 + r)*128 + m)*144 + mt*72 + v;
            split_bf(val, g_UAh[dst], g_UAl[dst]);
          }
        } else {
          int rr = z & 3, bb = z >> 2;
          int gc = p*CG + cc;
          outp[(long)bb*65536 + (2*m + (rr >> 1))*256 + 2*gc + (rr & 1)] = val;
        }
      }
    }
    __syncthreads();
  }
}

// ===================== launch ===============================================
extern "C" void kernel_launch(void* const* d_in, const int* in_sizes, int n_in,
                              void* d_out, int out_size)
{
  const float* x = (const float*)d_in[0];
  const float* w = (const float*)(n_in > 1 ? d_in[1] : d_in[0]);
  const float* bias = (const float*)(n_in > 2 ? d_in[2] : d_in[0]);
  for (int i = 0; i < n_in; i++){
    if (in_sizes[i] == 4*64*128*128) x = (const float*)d_in[i];
    else if (in_sizes[i] == 64*25)   w = (const float*)d_in[i];
    else if (in_sizes[i] == 64)      bias = (const float*)d_in[i];
  }
  float* out = (float*)d_out;

  constexpr int SM96  = 2*(2*128*80 + 2*96*80);    // 71680 (stages 1,2)
  constexpr int SM128 = 2*(2*128*80 + 2*128*80);   // 81920 (stage 3)
  cudaFuncSetAttribute(mma_k<1>, cudaFuncAttributeMaxDynamicSharedMemorySize, SM96);
  cudaFuncSetAttribute(mma_k<2>, cudaFuncAttributeMaxDynamicSharedMemorySize, SM96);
  cudaFuncSetAttribute(mma_k<3>, cudaFuncAttributeMaxDynamicSharedMemorySize, SM128);

  k_build<<<(160016+255)/256, 256>>>();            // #1
  k_H   <<<(64*136*69+255)/256, 256>>>(w, bias);   // #2
  gemm0_k<<<dim3(1,2,256), 256>>>(x);              // #3: Tsp (symmetry-halved)
  mma_k<1><<<dim3(2,272,1), 256, SM96>>>(out);     // #4: Yt = Tsp * MB2t^T
  k_Z   <<<(256*69*68+255)/256, 256>>>();          // #5: Z = Y .* H (flat grid)
  mma_k<2><<<dim3(3,2,256), 256, SM96>>>(out);     // #6: U -> g_UA (profiled)
  mma_k<3><<<dim3(1024,1,1), 256, SM128>>>(out);   // #7: out
}